// round 5
// baseline (speedup 1.0000x reference)
#include <cuda_runtime.h>
#include <cstdint>

#define B_ 64
#define T_ 4096
#define H_ 128

// Scratch for layer-0 input projection (alloc-free rule: __device__ global).
__device__ float g_xp0[(size_t)B_ * T_ * H_];

// ---------------------------------------------------------------------------
// Packed fp32x2 ops (Blackwell sm_100a+).
// ---------------------------------------------------------------------------
union F2U { float2 f; unsigned long long u; };

__device__ __forceinline__ float2 ffma2(float2 a, float2 b, float2 c) {
    F2U A, Bv, C, D;
    A.f = a; Bv.f = b; C.f = c;
    asm("fma.rn.f32x2 %0, %1, %2, %3;" : "=l"(D.u) : "l"(A.u), "l"(Bv.u), "l"(C.u));
    return D.f;
}

__device__ __forceinline__ float2 fadd2(float2 a, float2 b) {
    F2U A, Bv, D;
    A.f = a; Bv.f = b;
    asm("add.rn.f32x2 %0, %1, %2;" : "=l"(D.u) : "l"(A.u), "l"(Bv.u));
    return D.f;
}

// Hardware tanh (sm_75+): single MUFU op, ~1e-4 abs error.
__device__ __forceinline__ float tanh_approx(float x) {
    float r;
    asm("tanh.approx.f32 %0, %1;" : "=f"(r) : "f"(x));
    return r;
}

// 64-length partial dot: register row-half (32 float2) x smem half-vector
// (16 float4 broadcasts). 4 independent accumulator chains (depth 8).
__device__ __forceinline__ float dot64(const float2* __restrict__ w,
                                       const float4* __restrict__ hv) {
    float2 a0 = make_float2(0.f, 0.f), a1 = a0, a2 = a0, a3 = a0;
    #pragma unroll
    for (int i = 0; i < 16; i += 2) {
        float4 hA = hv[i];
        float4 hB = hv[i + 1];
        a0 = ffma2(make_float2(hA.x, hA.y), w[2 * i + 0], a0);
        a1 = ffma2(make_float2(hA.z, hA.w), w[2 * i + 1], a1);
        a2 = ffma2(make_float2(hB.x, hB.y), w[2 * i + 2], a2);
        a3 = ffma2(make_float2(hB.z, hB.w), w[2 * i + 3], a3);
    }
    float2 t0 = fadd2(a0, a1);
    float2 t1 = fadd2(a2, a3);
    t0 = fadd2(t0, t1);
    return t0.x + t0.y;
}

// ---------------------------------------------------------------------------
// Kernel A: xp0 = x @ W_ih0^T + b_ih0 + b_hh0   (unchanged — known good)
// ---------------------------------------------------------------------------
__global__ void __launch_bounds__(512, 1) xp0_gemm(
    const float* __restrict__ x,
    const float* __restrict__ W_ih0,
    const float* __restrict__ b_ih0,
    const float* __restrict__ b_hh0)
{
    __shared__ float A_s[128][32];
    __shared__ float W_s[32][128];

    const int tid  = threadIdx.x;
    const int m0   = blockIdx.x * 128;
    const int row0 = (tid >> 5) * 8;
    const int col0 = (tid & 31) * 4;

    float2 acc[8][2];
    #pragma unroll
    for (int i = 0; i < 8; i++) {
        acc[i][0] = make_float2(0.f, 0.f);
        acc[i][1] = make_float2(0.f, 0.f);
    }

    for (int kk = 0; kk < 128; kk += 32) {
        __syncthreads();
        #pragma unroll
        for (int l = 0; l < 2; l++) {
            int idx = tid + l * 512;
            int r = idx >> 3, q4 = idx & 7;
            float4 v = *(const float4*)(x + (size_t)(m0 + r) * 128 + kk + q4 * 4);
            *(float4*)&A_s[r][q4 * 4] = v;
        }
        #pragma unroll
        for (int l = 0; l < 2; l++) {
            int idx = tid + l * 512;
            int j = idx & 127, q4 = idx >> 7;
            float4 v = *(const float4*)(W_ih0 + j * 128 + kk + q4 * 4);
            W_s[q4 * 4 + 0][j] = v.x;
            W_s[q4 * 4 + 1][j] = v.y;
            W_s[q4 * 4 + 2][j] = v.z;
            W_s[q4 * 4 + 3][j] = v.w;
        }
        __syncthreads();

        #pragma unroll
        for (int k4 = 0; k4 < 8; k4++) {
            float4 a[8];
            #pragma unroll
            for (int i = 0; i < 8; i++)
                a[i] = *(const float4*)&A_s[row0 + i][k4 * 4];
            #pragma unroll
            for (int u = 0; u < 4; u++) {
                float4 w = *(const float4*)&W_s[k4 * 4 + u][col0];
                float2 wlo = make_float2(w.x, w.y);
                float2 whi = make_float2(w.z, w.w);
                #pragma unroll
                for (int i = 0; i < 8; i++) {
                    float av = (u == 0) ? a[i].x : (u == 1) ? a[i].y
                             : (u == 2) ? a[i].z : a[i].w;
                    float2 a2 = make_float2(av, av);
                    acc[i][0] = ffma2(a2, wlo, acc[i][0]);
                    acc[i][1] = ffma2(a2, whi, acc[i][1]);
                }
            }
        }
    }

    float4 bias;
    bias.x = b_ih0[col0 + 0] + b_hh0[col0 + 0];
    bias.y = b_ih0[col0 + 1] + b_hh0[col0 + 1];
    bias.z = b_ih0[col0 + 2] + b_hh0[col0 + 2];
    bias.w = b_ih0[col0 + 3] + b_hh0[col0 + 3];

    #pragma unroll
    for (int i = 0; i < 8; i++) {
        float4 o;
        o.x = acc[i][0].x + bias.x;
        o.y = acc[i][0].y + bias.y;
        o.z = acc[i][1].x + bias.z;
        o.w = acc[i][1].y + bias.w;
        *(float4*)(g_xp0 + (size_t)(m0 + row0 + i) * 128 + col0) = o;
    }
}

// ---------------------------------------------------------------------------
// Kernel B: fused 2-layer recurrence, pipelined by matrix, k-split by 2.
// 768 threads = 3 groups x 256. Thread (grp, j = (tid&255)>>1, c = tid&1)
// owns row j, k-half c of its group's matrix: 32 float2 weight regs.
// 6 warps/SMSP hide LDS latency + tails. One barrier per step.
// shfl_xor(1) combines the two k-halves; the c==0 lane finishes the row.
//
// Iteration it (0..T+1), pr = it&1:
//   A: h0[it]   = tanh(xp0[it] + h0[it-1]·W_hh0)   reads h0s[pr] -> h0s[pr^1]
//   B: D1[it-1] = h0[it-1]·W_ih1                   reads h0s[pr] -> d1s[pr]
//   C: h1[it-2] = tanh(b1 + D1[it-2] + h1[it-3]·W_hh1)
//                 reads h1s[pr^1], d1s[pr^1] -> h1s[pr], out1
// ---------------------------------------------------------------------------
__global__ void __launch_bounds__(768, 1) rnn_recurrence(
    const float* __restrict__ W_hh0,
    const float* __restrict__ W_ih1,
    const float* __restrict__ W_hh1,
    const float* __restrict__ b_ih1,
    const float* __restrict__ b_hh1,
    float* __restrict__ out1,     // [B,T,H]
    float* __restrict__ hidden)   // [2,B,H]
{
    __shared__ float h0s[2][128];
    __shared__ float h1s[2][128];
    __shared__ float d1s[2][128];

    const int b   = blockIdx.x;
    const int tid = threadIdx.x;
    const int grp = tid >> 8;        // 0=A, 1=B, 2=C (8 warps each)
    const int g   = tid & 255;
    const int j   = g >> 1;          // row 0..127
    const int c   = g & 1;           // k-half

    if (tid < 128) {
        h0s[0][tid] = 0.f; h0s[1][tid] = 0.f;
        h1s[0][tid] = 0.f; h1s[1][tid] = 0.f;
        d1s[0][tid] = 0.f; d1s[1][tid] = 0.f;
    }

    // Row-half of this group's matrix -> 32 float2 (64 regs).
    const float* wsrc = ((grp == 0) ? W_hh0 : (grp == 1) ? W_ih1 : W_hh1)
                        + j * 128 + c * 64;
    float2 w[32];
    {
        const float2* p = (const float2*)wsrc;
        #pragma unroll
        for (int i = 0; i < 32; i++) w[i] = p[i];
    }

    const float bias1 = b_ih1[j] + b_hh1[j];   // group C only
    const bool lead = (c == 0);

    // Group A xp0 prefetch (distance 2), lead lanes only.
    const float* xp = g_xp0 + (size_t)b * T_ * H_ + j;
    float xpA = 0.f, xpB = 0.f;
    if (grp == 0 && lead) { xpA = __ldcg(&xp[0]); xpB = __ldcg(&xp[H_]); }

    float* outb = out1 + (size_t)b * T_ * H_ + j;
    float h0_last = 0.f, h1_last = 0.f;

    __syncthreads();

    #pragma unroll 1
    for (int it = 0; it < T_ + 2; it++) {
        const int pr = it & 1;
        if (grp == 0) {
            if (it < T_) {
                float s = dot64(w, (const float4*)&h0s[pr][c * 64]);
                s += __shfl_xor_sync(0xffffffffu, s, 1);
                if (lead) {
                    float h0new = tanh_approx(s + xpA);
                    xpA = xpB;
                    int tp = it + 2; tp = (tp < T_) ? tp : (T_ - 1);
                    xpB = __ldcg(&xp[(size_t)tp * H_]);
                    h0s[pr ^ 1][j] = h0new;
                    h0_last = h0new;
                }
            }
        } else if (grp == 1) {
            if (it >= 1 && it <= T_) {
                float s = dot64(w, (const float4*)&h0s[pr][c * 64]);
                s += __shfl_xor_sync(0xffffffffu, s, 1);
                if (lead) d1s[pr][j] = s;
            }
        } else {
            if (it >= 2) {
                float s = dot64(w, (const float4*)&h1s[pr ^ 1][c * 64]);
                s += __shfl_xor_sync(0xffffffffu, s, 1);
                if (lead) {
                    float h1new = tanh_approx(s + d1s[pr ^ 1][j] + bias1);
                    h1s[pr][j] = h1new;
                    __stcg(&outb[(size_t)(it - 2) * H_], h1new);
                    h1_last = h1new;
                }
            }
        }
        __syncthreads();
    }

    if (grp == 0 && lead) hidden[(size_t)b * H_ + j] = h0_last;
    if (grp == 2 && lead) hidden[(size_t)B_ * H_ + (size_t)b * H_ + j] = h1_last;
}

// ---------------------------------------------------------------------------
// kernel_launch
// Inputs (metadata order): x, W_ih0, W_hh0, b_ih0, b_hh0, W_ih1, W_hh1,
//                          b_ih1, b_hh1.
// Output: out1 [B,T,H] followed by hidden_state [2,B,H].
// ---------------------------------------------------------------------------
extern "C" void kernel_launch(void* const* d_in, const int* in_sizes, int n_in,
                              void* d_out, int out_size) {
    const float* x      = (const float*)d_in[0];
    const float* W_ih0  = (const float*)d_in[1];
    const float* W_hh0  = (const float*)d_in[2];
    const float* b_ih0  = (const float*)d_in[3];
    const float* b_hh0  = (const float*)d_in[4];
    const float* W_ih1  = (const float*)d_in[5];
    const float* W_hh1  = (const float*)d_in[6];
    const float* b_ih1  = (const float*)d_in[7];
    const float* b_hh1  = (const float*)d_in[8];

    float* out1   = (float*)d_out;
    float* hidden = (float*)d_out + (size_t)B_ * T_ * H_;

    xp0_gemm<<<(B_ * T_) / 128, 512>>>(x, W_ih0, b_ih0, b_hh0);
    rnn_recurrence<<<B_, 768>>>(W_hh0, W_ih1, W_hh1, b_ih1, b_hh1, out1, hidden);
}